// round 10
// baseline (speedup 1.0000x reference)
#include <cuda_runtime.h>
#include <cuda_fp16.h>
#include <stdint.h>

#define BATCH 4
#define SEQ   4096
#define DIM   1024
#define QKVN  3072

// CTA tile 128x128, 4 warps of 64x64, 128 threads
#define TM 128
#define TN 128
#define KC 64
#define PITCH 132   // fp32 stage pitch

#define NELT_X ((long)BATCH*SEQ*DIM)   // 16,777,216
#define NELT_W ((long)QKVN*DIM)        //  3,145,728
#define NELT_S ((long)BATCH*SEQ*SEQ)   // 67,108,864

// -------- scratch (device globals; no allocations allowed) --------
__device__ __half g_xh [NELT_X];                 // x: single f16
__device__ __half g_Wh [NELT_W];                 // W: single f16
__device__ __half g_Qh [NELT_X];                 // Q: single f16
__device__ __half g_Kh [NELT_X];                 // K: single f16
__device__ __half g_Vth[NELT_X];                 // V transposed [B][DIM][SEQ]
__device__ __half g_Ph [NELT_S];                 // unnormalized exp(scores)
__device__ float  g_rowsum[(long)BATCH * SEQ];

extern __shared__ char dynsmem[];

// ---------------- helpers ----------------
__device__ __forceinline__ uint32_t cvta_smem(const void* p) {
    uint32_t a;
    asm("{ .reg .u64 t; cvta.to.shared.u64 t, %1; cvt.u32.u64 %0, t; }" : "=r"(a) : "l"(p));
    return a;
}
__device__ __forceinline__ void cp16(uint32_t s, const void* g) {
    asm volatile("cp.async.cg.shared.global [%0], [%1], 16;" :: "r"(s), "l"(g));
}
__device__ __forceinline__ void cp_commit() { asm volatile("cp.async.commit_group;" ::: "memory"); }
template <int N> __device__ __forceinline__ void cp_wait() {
    asm volatile("cp.async.wait_group %0;" :: "n"(N) : "memory");
}
__device__ __forceinline__ uint32_t swz(uint32_t off) { return off ^ ((off >> 3) & 0x70); }

__device__ __forceinline__ void ldsm4(uint32_t& r0, uint32_t& r1, uint32_t& r2, uint32_t& r3,
                                      uint32_t addr) {
    asm volatile("ldmatrix.sync.aligned.m8n8.x4.shared.b16 {%0,%1,%2,%3}, [%4];"
                 : "=r"(r0), "=r"(r1), "=r"(r2), "=r"(r3) : "r"(addr));
}
__device__ __forceinline__ void mma16816(float* c, const uint32_t* a, const uint32_t* b) {
    asm volatile(
        "mma.sync.aligned.m16n8k16.row.col.f32.f16.f16.f32 "
        "{%0,%1,%2,%3}, {%4,%5,%6,%7}, {%8,%9}, {%0,%1,%2,%3};"
        : "+f"(c[0]), "+f"(c[1]), "+f"(c[2]), "+f"(c[3])
        : "r"(a[0]), "r"(a[1]), "r"(a[2]), "r"(a[3]), "r"(b[0]), "r"(b[1]));
}

// load [128 x 64] f16 K-major tile into SW128-swizzled smem; 128 threads, 8 chunks each
__device__ __forceinline__ void load_tile(uint32_t sb, const __half* __restrict__ src,
                                          long K, long row0, long k0) {
    const int tid = threadIdx.x;
#pragma unroll
    for (int i = 0; i < 8; i++) {
        const int idx = tid + i * 128;        // 0..1023
        const int r = idx >> 3, ch = idx & 7;
        const uint32_t off = swz((uint32_t)(r * 128 + ch * 16));
        cp16(sb + off, src + (row0 + r) * K + k0 + ch * 8);
    }
}

// ----------------------------------------------------------------------------
// gemm1: C[128,128] = Ah * Bh^T (single f16), 4 warps of 64x64.
// 3-stage cp.async pipeline with ONE barrier per k-iter:
//   wait<1>; sync; load(it+2); commit; mma(it)
// Buffer written at iter it was read at it-1; all warps passed this iter's sync
// after their it-1 MMAs, so no trailing barrier is needed.
// Leaves accumulators in registers (acc). NO trailing syncthreads.
// ----------------------------------------------------------------------------
__device__ __forceinline__ void gemm1(const __half* __restrict__ Ah,
                                      const __half* __restrict__ Bh,
                                      long bm, long bn, int K, float acc[4][8][4]) {
    const uint32_t STAGE = 32 * 1024;
    const uint32_t OA = 0, OB = 16 * 1024;
    const uint32_t smb = cvta_smem(dynsmem);
    const int wid = threadIdx.x >> 5, lane = threadIdx.x & 31;
    const int wm = wid & 1, wn = wid >> 1;   // 2x2 warp grid, 64x64 tiles
    const int NIT = K / KC;

#pragma unroll
    for (int i = 0; i < 4; i++)
#pragma unroll
        for (int j = 0; j < 8; j++)
#pragma unroll
            for (int k = 0; k < 4; k++) acc[i][j][k] = 0.0f;

    const uint32_t aPart = (uint32_t)((lane & 15) * 128 + (lane >> 4) * 16);
    const uint32_t bPart = (uint32_t)((((lane & 7) + ((lane >> 4) << 3)) * 128) + ((lane >> 3) & 1) * 16);

    // prologue: stages 0,1 -> groups 0,1
    load_tile(smb + 0 * STAGE + OA, Ah, K, bm, 0);
    load_tile(smb + 0 * STAGE + OB, Bh, K, bn, 0);
    cp_commit();
    load_tile(smb + 1 * STAGE + OA, Ah, K, bm, KC);
    load_tile(smb + 1 * STAGE + OB, Bh, K, bn, KC);
    cp_commit();

    int stg = 0;             // = it % 3
    int nstg = 2;            // = (it+2) % 3
    for (int it = 0; it < NIT; ++it) {
        cp_wait<1>();         // completes group it (2 outstanding at entry)
        __syncthreads();      // cross-thread visibility + buffer-reuse safety
        if (it + 2 < NIT) {
            const uint32_t nb = smb + (uint32_t)nstg * STAGE;
            const long k0 = (long)(it + 2) * KC;
            load_tile(nb + OA, Ah, K, bm, k0);
            load_tile(nb + OB, Bh, K, bn, k0);
        }
        cp_commit();          // group it+2 (possibly empty; keeps numbering)

        const uint32_t cur = smb + (uint32_t)stg * STAGE;
#pragma unroll
        for (int ks = 0; ks < KC / 16; ++ks) {
            uint32_t ah[4][4], bh[4][4];
#pragma unroll
            for (int mt = 0; mt < 4; ++mt) {
                const uint32_t off = (uint32_t)((wm * 64 + mt * 16) * 128 + ks * 32) + aPart;
                ldsm4(ah[mt][0], ah[mt][1], ah[mt][2], ah[mt][3], cur + OA + swz(off));
            }
#pragma unroll
            for (int nt = 0; nt < 4; ++nt) {
                const uint32_t off = (uint32_t)((wn * 64 + nt * 16) * 128 + ks * 32) + bPart;
                ldsm4(bh[nt][0], bh[nt][1], bh[nt][2], bh[nt][3], cur + OB + swz(off));
            }
#pragma unroll
            for (int mt = 0; mt < 4; ++mt)
#pragma unroll
                for (int nt = 0; nt < 4; ++nt) {
                    mma16816(acc[mt][nt * 2],     ah[mt], &bh[nt][0]);
                    mma16816(acc[mt][nt * 2 + 1], ah[mt], &bh[nt][2]);
                }
        }
        stg = (stg == 2) ? 0 : stg + 1;
        nstg = (nstg == 2) ? 0 : nstg + 1;
    }
}

// dump accs to fp32 smem stage (sync before: MMAs of all warps still read the
// buffers the stage overlays; sync after: make stage visible to readers)
__device__ __forceinline__ void acc_to_stage(float acc[4][8][4]) {
    __syncthreads();
    float* stage = (float*)dynsmem;
    const int wid = threadIdx.x >> 5, lane = threadIdx.x & 31;
    const int wm = wid & 1, wn = wid >> 1;
    const int rl = lane >> 2, cl = (lane & 3) * 2;
#pragma unroll
    for (int mt = 0; mt < 4; ++mt)
#pragma unroll
        for (int n8 = 0; n8 < 8; ++n8) {
            const int r = wm * 64 + mt * 16 + rl;
            const int c = wn * 64 + n8 * 8 + cl;
            *(float2*)&stage[r * PITCH + c] = make_float2(acc[mt][n8][0], acc[mt][n8][1]);
            *(float2*)&stage[(r + 8) * PITCH + c] = make_float2(acc[mt][n8][2], acc[mt][n8][3]);
        }
    __syncthreads();
}

// ---------------- convert (fp32 -> single f16); dst chosen IN DEVICE CODE ----------------
__global__ void __launch_bounds__(256) convert_h(const float* __restrict__ in, int mode) {
    __half* dst = mode ? g_Wh : g_xh;
    const long i = (long)blockIdx.x * 256 + threadIdx.x;
    float4 v = ((const float4*)in)[i];
    __half2 a, b;
    a.x = __float2half_rn(v.x); a.y = __float2half_rn(v.y);
    b.x = __float2half_rn(v.z); b.y = __float2half_rn(v.w);
    uint2 o;
    o.x = *reinterpret_cast<uint32_t*>(&a);
    o.y = *reinterpret_cast<uint32_t*>(&b);
    *(uint2*)(dst + i * 4) = o;
}

// ---------------- zero g_rowsum (graph-replay safe: runs every launch) ----------------
__global__ void __launch_bounds__(256) zero_rowsum() {
    g_rowsum[blockIdx.x * 256 + threadIdx.x] = 0.0f;
}

// ---------------- Kernel 1: QKV projection ----------------
__global__ void __launch_bounds__(128, 2) qkv_gemm_tc(const float* __restrict__ bias) {
    const long bm = (long)blockIdx.y * TM;
    const long bn = (long)blockIdx.x * TN;
    float acc[4][8][4];
    gemm1(g_xh, g_Wh, bm, bn, DIM, acc);
    acc_to_stage(acc);

    float* stage = (float*)dynsmem;
    const int tid = threadIdx.x;
    const int sel = (int)(bn >> 10);        // 0:Q 1:K 2:V
    const long nc0 = bn & 1023;
    if (sel < 2) {
        __half* dst = sel ? g_Kh : g_Qh;
        for (int idx = tid; idx < TM * TN / 2; idx += 128) {
            const int row = idx >> 6, col = (idx & 63) * 2;
            const float v0 = stage[row * PITCH + col]     + bias[bn + col];
            const float v1 = stage[row * PITCH + col + 1] + bias[bn + col + 1];
            __half2 H; H.x = __float2half_rn(v0); H.y = __float2half_rn(v1);
            *(__half2*)(dst + (bm + row) * DIM + nc0 + col) = H;
        }
    } else {
        // V: write transposed Vt[b][n'][s] (consecutive tid -> consecutive s)
        const long b = bm >> 12, s0 = bm & 4095;
        for (int idx = tid; idx < TM * TN; idx += 128) {
            const int row = idx & 127, col = idx >> 7;
            const float v = stage[row * PITCH + col] + bias[bn + col];
            g_Vth[(b * DIM + nc0 + col) * SEQ + s0 + row] = __float2half_rn(v);
        }
    }
}

// ---------------- Kernel 2: P̂ = exp((Q K^T)/32) + fused partial rowsum ----------------
__global__ void __launch_bounds__(128, 2) scores_gemm_tc() {
    const int z = blockIdx.z;
    const long bm = (long)blockIdx.y * TM;
    const long bn = (long)blockIdx.x * TN;
    const long qo = (long)z * SEQ * DIM;
    float acc[4][8][4];
    gemm1(g_Qh + qo, g_Kh + qo, bm, bn, DIM, acc);

    // exp in registers, then one stage dump
#pragma unroll
    for (int mt = 0; mt < 4; ++mt)
#pragma unroll
        for (int n8 = 0; n8 < 8; ++n8)
#pragma unroll
            for (int k = 0; k < 4; ++k)
                acc[mt][n8][k] = __expf(acc[mt][n8][k] * 0.03125f);
    acc_to_stage(acc);

    float* stage = (float*)dynsmem;
    const long so = (long)z * SEQ * SEQ;
    const int tid = threadIdx.x;
    // single read pass: f16 convert + store
    for (int idx = tid; idx < TM * TN / 2; idx += 128) {
        const int row = idx >> 6, col = (idx & 63) * 2;
        const float2 e = *(const float2*)&stage[row * PITCH + col];
        __half2 H; H.x = __float2half_rn(e.x); H.y = __float2half_rn(e.y);
        *(__half2*)(g_Ph + so + (bm + row) * SEQ + bn + col) = H;
    }
    // rowsum: thread t sums row t (fp32 e-values), one atomic per row
    {
        const int row = tid;
        float s = 0.0f;
        const float2* rp = (const float2*)&stage[row * PITCH];
#pragma unroll 16
        for (int c = 0; c < 64; ++c) { float2 v = rp[c]; s += v.x + v.y; }
        atomicAdd(&g_rowsum[(long)z * SEQ + bm + row], s);
    }
}

// ---------------- Kernel 3: out = (P̂ @ V) / rowsum — direct register epilogue ----------------
__global__ void __launch_bounds__(128, 2) pv_gemm_tc(float* __restrict__ out) {
    const int z = blockIdx.z;
    const long bm = (long)blockIdx.y * TM;
    const long bn = (long)blockIdx.x * TN;
    const long po = (long)z * SEQ * SEQ;
    const long vo = (long)z * DIM * SEQ;
    float acc[4][8][4];
    gemm1(g_Ph + po, g_Vth + vo, bm, bn, SEQ, acc);

    float* O = out + (long)z * SEQ * DIM;
    const float* rs = g_rowsum + (long)z * SEQ;
    const int wid = threadIdx.x >> 5, lane = threadIdx.x & 31;
    const int wm = wid & 1, wn = wid >> 1;
    const int rl = lane >> 2, cl = (lane & 3) * 2;
#pragma unroll
    for (int mt = 0; mt < 4; ++mt) {
        const long ra = bm + wm * 64 + mt * 16 + rl;
        const float ia = 1.0f / rs[ra];
        const float ib = 1.0f / rs[ra + 8];
#pragma unroll
        for (int n8 = 0; n8 < 8; ++n8) {
            const long c = bn + wn * 64 + n8 * 8 + cl;
            *(float2*)&O[ra * DIM + c] = make_float2(acc[mt][n8][0] * ia, acc[mt][n8][1] * ia);
            *(float2*)&O[(ra + 8) * DIM + c] = make_float2(acc[mt][n8][2] * ib, acc[mt][n8][3] * ib);
        }
    }
}

// ---------------------------------------------------------------------------
extern "C" void kernel_launch(void* const* d_in, const int* in_sizes, int n_in,
                              void* d_out, int out_size) {
    const float* x1 = nullptr;
    const float* W = nullptr;
    const float* bias = nullptr;
    for (int i = 0; i < n_in; i++) {
        if (in_sizes[i] == (int)(BATCH * SEQ * DIM)) x1 = (const float*)d_in[i];
        else if (in_sizes[i] == (int)(QKVN * DIM))   W = (const float*)d_in[i];
        else if (in_sizes[i] == QKVN)                bias = (const float*)d_in[i];
    }
    float* out = (float*)d_out;

    const int SM_BYTES = 96 * 1024;   // 3x32KB stages; fp32 stage overlay 67.6KB

    cudaFuncSetAttribute(qkv_gemm_tc, cudaFuncAttributeMaxDynamicSharedMemorySize, SM_BYTES);
    cudaFuncSetAttribute(scores_gemm_tc, cudaFuncAttributeMaxDynamicSharedMemorySize, SM_BYTES);
    cudaFuncSetAttribute(pv_gemm_tc, cudaFuncAttributeMaxDynamicSharedMemorySize, SM_BYTES);

    zero_rowsum<<<BATCH * SEQ / 256, 256>>>();
    convert_h<<<NELT_X / 1024, 256>>>(x1, 0);
    convert_h<<<NELT_W / 1024, 256>>>(W, 1);
    qkv_gemm_tc<<<dim3(QKVN / TN, (BATCH * SEQ) / TM), 128, SM_BYTES>>>(bias);
    scores_gemm_tc<<<dim3(SEQ / TN, SEQ / TM, BATCH), 128, SM_BYTES>>>();
    pv_gemm_tc<<<dim3(DIM / TN, SEQ / TM, BATCH), 128, SM_BYTES>>>(out);
}

// round 11
// speedup vs baseline: 1.0811x; 1.0811x over previous
#include <cuda_runtime.h>
#include <cuda_fp16.h>
#include <stdint.h>

#define BATCH 4
#define SEQ   4096
#define DIM   1024
#define QKVN  3072

// CTA tile 128x128, 4 warps of 64x64, 128 threads
#define TM 128
#define TN 128
#define KC 64
#define PITCH 132   // fp32 stage pitch (V-transpose epilogue only)

#define NELT_X ((long)BATCH*SEQ*DIM)   // 16,777,216
#define NELT_W ((long)QKVN*DIM)        //  3,145,728
#define NELT_S ((long)BATCH*SEQ*SEQ)   // 67,108,864

// -------- scratch (device globals; no allocations allowed) --------
__device__ __half g_xh [NELT_X];                 // x: single f16
__device__ __half g_Wh [NELT_W];                 // W: single f16
__device__ __half g_Qh [NELT_X];                 // Q: single f16
__device__ __half g_Kh [NELT_X];                 // K: single f16
__device__ __half g_Vth[NELT_X];                 // V transposed [B][DIM][SEQ]
__device__ __half g_Ph [NELT_S];                 // unnormalized exp(scores)
__device__ float  g_rowsum[(long)BATCH * SEQ];

extern __shared__ char dynsmem[];

// ---------------- helpers ----------------
__device__ __forceinline__ uint32_t cvta_smem(const void* p) {
    uint32_t a;
    asm("{ .reg .u64 t; cvta.to.shared.u64 t, %1; cvt.u32.u64 %0, t; }" : "=r"(a) : "l"(p));
    return a;
}
__device__ __forceinline__ void cp16(uint32_t s, const void* g) {
    asm volatile("cp.async.cg.shared.global [%0], [%1], 16;" :: "r"(s), "l"(g));
}
__device__ __forceinline__ void cp_commit() { asm volatile("cp.async.commit_group;" ::: "memory"); }
template <int N> __device__ __forceinline__ void cp_wait() {
    asm volatile("cp.async.wait_group %0;" :: "n"(N) : "memory");
}
__device__ __forceinline__ uint32_t swz(uint32_t off) { return off ^ ((off >> 3) & 0x70); }

__device__ __forceinline__ void ldsm4(uint32_t& r0, uint32_t& r1, uint32_t& r2, uint32_t& r3,
                                      uint32_t addr) {
    asm volatile("ldmatrix.sync.aligned.m8n8.x4.shared.b16 {%0,%1,%2,%3}, [%4];"
                 : "=r"(r0), "=r"(r1), "=r"(r2), "=r"(r3) : "r"(addr));
}
__device__ __forceinline__ void mma16816(float* c, const uint32_t* a, const uint32_t* b) {
    asm volatile(
        "mma.sync.aligned.m16n8k16.row.col.f32.f16.f16.f32 "
        "{%0,%1,%2,%3}, {%4,%5,%6,%7}, {%8,%9}, {%0,%1,%2,%3};"
        : "+f"(c[0]), "+f"(c[1]), "+f"(c[2]), "+f"(c[3])
        : "r"(a[0]), "r"(a[1]), "r"(a[2]), "r"(a[3]), "r"(b[0]), "r"(b[1]));
}

// load [128 x 64] f16 K-major tile into SW128-swizzled smem; 128 threads, 8 chunks each
__device__ __forceinline__ void load_tile(uint32_t sb, const __half* __restrict__ src,
                                          long K, long row0, long k0) {
    const int tid = threadIdx.x;
#pragma unroll
    for (int i = 0; i < 8; i++) {
        const int idx = tid + i * 128;        // 0..1023
        const int r = idx >> 3, ch = idx & 7;
        const uint32_t off = swz((uint32_t)(r * 128 + ch * 16));
        cp16(sb + off, src + (row0 + r) * K + k0 + ch * 8);
    }
}

// one ks-step (16 k-depth): 8 LDSM + 32 MMA for a 64x64 warp tile
__device__ __forceinline__ void mma_step(uint32_t cur, int ks, int wm, int wn,
                                         uint32_t aPart, uint32_t bPart,
                                         float acc[4][8][4]) {
    const uint32_t OA = 0, OB = 16 * 1024;
    uint32_t ah[4][4], bh[4][4];
#pragma unroll
    for (int mt = 0; mt < 4; ++mt) {
        const uint32_t off = (uint32_t)((wm * 64 + mt * 16) * 128 + ks * 32) + aPart;
        ldsm4(ah[mt][0], ah[mt][1], ah[mt][2], ah[mt][3], cur + OA + swz(off));
    }
#pragma unroll
    for (int nt = 0; nt < 4; ++nt) {
        const uint32_t off = (uint32_t)((wn * 64 + nt * 16) * 128 + ks * 32) + bPart;
        ldsm4(bh[nt][0], bh[nt][1], bh[nt][2], bh[nt][3], cur + OB + swz(off));
    }
#pragma unroll
    for (int mt = 0; mt < 4; ++mt)
#pragma unroll
        for (int nt = 0; nt < 4; ++nt) {
            mma16816(acc[mt][nt * 2],     ah[mt], &bh[nt][0]);
            mma16816(acc[mt][nt * 2 + 1], ah[mt], &bh[nt][2]);
        }
}

// ----------------------------------------------------------------------------
// gemm1: C[128,128] = Ah * Bh^T (single f16), 4 warps of 64x64, 3-stage pipeline.
// k-loop order: wait; sync; [ks=0 MMA]; issue loads(it+2); commit; [ks=1..3].
// Loads issue under the ks=0 MMA shadow instead of blocking the first LDSMs.
// Leaves accumulators in registers. NO trailing syncthreads.
// ----------------------------------------------------------------------------
__device__ __forceinline__ void gemm1(const __half* __restrict__ Ah,
                                      const __half* __restrict__ Bh,
                                      long bm, long bn, int K, float acc[4][8][4]) {
    const uint32_t STAGE = 32 * 1024;
    const uint32_t OA = 0, OB = 16 * 1024;
    const uint32_t smb = cvta_smem(dynsmem);
    const int wid = threadIdx.x >> 5, lane = threadIdx.x & 31;
    const int wm = wid & 1, wn = wid >> 1;
    const int NIT = K / KC;

#pragma unroll
    for (int i = 0; i < 4; i++)
#pragma unroll
        for (int j = 0; j < 8; j++)
#pragma unroll
            for (int k = 0; k < 4; k++) acc[i][j][k] = 0.0f;

    const uint32_t aPart = (uint32_t)((lane & 15) * 128 + (lane >> 4) * 16);
    const uint32_t bPart = (uint32_t)((((lane & 7) + ((lane >> 4) << 3)) * 128) + ((lane >> 3) & 1) * 16);

    // prologue: stages 0,1 -> groups 0,1
    load_tile(smb + 0 * STAGE + OA, Ah, K, bm, 0);
    load_tile(smb + 0 * STAGE + OB, Bh, K, bn, 0);
    cp_commit();
    load_tile(smb + 1 * STAGE + OA, Ah, K, bm, KC);
    load_tile(smb + 1 * STAGE + OB, Bh, K, bn, KC);
    cp_commit();

    int stg = 0, nstg = 2;
    for (int it = 0; it < NIT; ++it) {
        cp_wait<1>();         // group it complete
        __syncthreads();      // all warps' portions visible; prior reads done
        const uint32_t cur = smb + (uint32_t)stg * STAGE;

        mma_step(cur, 0, wm, wn, aPart, bPart, acc);   // ks=0 first

        if (it + 2 < NIT) {   // loads issue under ks=0/1 MMA shadow
            const uint32_t nb = smb + (uint32_t)nstg * STAGE;
            const long k0 = (long)(it + 2) * KC;
            load_tile(nb + OA, Ah, K, bm, k0);
            load_tile(nb + OB, Bh, K, bn, k0);
        }
        cp_commit();          // group it+2 (possibly empty)

#pragma unroll
        for (int ks = 1; ks < KC / 16; ++ks)
            mma_step(cur, ks, wm, wn, aPart, bPart, acc);

        stg = (stg == 2) ? 0 : stg + 1;
        nstg = (nstg == 2) ? 0 : nstg + 1;
    }
}

// dump accs to fp32 smem stage (only used by V-transpose epilogue)
__device__ __forceinline__ void acc_to_stage(float acc[4][8][4]) {
    __syncthreads();
    float* stage = (float*)dynsmem;
    const int wid = threadIdx.x >> 5, lane = threadIdx.x & 31;
    const int wm = wid & 1, wn = wid >> 1;
    const int rl = lane >> 2, cl = (lane & 3) * 2;
#pragma unroll
    for (int mt = 0; mt < 4; ++mt)
#pragma unroll
        for (int n8 = 0; n8 < 8; ++n8) {
            const int r = wm * 64 + mt * 16 + rl;
            const int c = wn * 64 + n8 * 8 + cl;
            *(float2*)&stage[r * PITCH + c] = make_float2(acc[mt][n8][0], acc[mt][n8][1]);
            *(float2*)&stage[(r + 8) * PITCH + c] = make_float2(acc[mt][n8][2], acc[mt][n8][3]);
        }
    __syncthreads();
}

// ---------------- convert (fp32 -> single f16); dst chosen IN DEVICE CODE ----------------
__global__ void __launch_bounds__(256) convert_h(const float* __restrict__ in, int mode) {
    __half* dst = mode ? g_Wh : g_xh;
    const long i = (long)blockIdx.x * 256 + threadIdx.x;
    float4 v = ((const float4*)in)[i];
    __half2 a, b;
    a.x = __float2half_rn(v.x); a.y = __float2half_rn(v.y);
    b.x = __float2half_rn(v.z); b.y = __float2half_rn(v.w);
    uint2 o;
    o.x = *reinterpret_cast<uint32_t*>(&a);
    o.y = *reinterpret_cast<uint32_t*>(&b);
    *(uint2*)(dst + i * 4) = o;
}

// ---------------- zero g_rowsum (graph-replay safe: runs every launch) ----------------
__global__ void __launch_bounds__(256) zero_rowsum() {
    g_rowsum[blockIdx.x * 256 + threadIdx.x] = 0.0f;
}

// ---------------- Kernel 1: QKV projection ----------------
__global__ void __launch_bounds__(128, 2) qkv_gemm_tc(const float* __restrict__ bias) {
    const long bm = (long)blockIdx.y * TM;
    const long bn = (long)blockIdx.x * TN;
    float acc[4][8][4];
    gemm1(g_xh, g_Wh, bm, bn, DIM, acc);

    const int sel = (int)(bn >> 10);        // 0:Q 1:K 2:V
    const long nc0 = bn & 1023;
    const int wid = threadIdx.x >> 5, lane = threadIdx.x & 31;
    const int wm = wid & 1, wn = wid >> 1;
    const int rl = lane >> 2, cl = (lane & 3) * 2;

    if (sel < 2) {
        // Q/K: register epilogue — bias add + f16 store straight from accs
        __half* dst = sel ? g_Kh : g_Qh;
#pragma unroll
        for (int mt = 0; mt < 4; ++mt) {
            const long ra = bm + wm * 64 + mt * 16 + rl;
#pragma unroll
            for (int n8 = 0; n8 < 8; ++n8) {
                const int c = wn * 64 + n8 * 8 + cl;
                const float b0 = bias[bn + c], b1 = bias[bn + c + 1];
                __half2 H0, H1;
                H0.x = __float2half_rn(acc[mt][n8][0] + b0);
                H0.y = __float2half_rn(acc[mt][n8][1] + b1);
                H1.x = __float2half_rn(acc[mt][n8][2] + b0);
                H1.y = __float2half_rn(acc[mt][n8][3] + b1);
                *(__half2*)(dst + ra * DIM + nc0 + c) = H0;
                *(__half2*)(dst + (ra + 8) * DIM + nc0 + c) = H1;
            }
        }
    } else {
        // V: transpose via stage
        acc_to_stage(acc);
        float* stage = (float*)dynsmem;
        const long b = bm >> 12, s0 = bm & 4095;
        for (int idx = threadIdx.x; idx < TM * TN; idx += 128) {
            const int row = idx & 127, col = idx >> 7;
            const float v = stage[row * PITCH + col] + bias[bn + col];
            g_Vth[(b * DIM + nc0 + col) * SEQ + s0 + row] = __float2half_rn(v);
        }
    }
}

// ---------------- Kernel 2: P̂ = exp((Q K^T)/32) — full register epilogue ----------------
__global__ void __launch_bounds__(128, 2) scores_gemm_tc() {
    const int z = blockIdx.z;
    const long bm = (long)blockIdx.y * TM;
    const long bn = (long)blockIdx.x * TN;
    const long qo = (long)z * SEQ * DIM;
    float acc[4][8][4];
    gemm1(g_Qh + qo, g_Kh + qo, bm, bn, DIM, acc);

    // exp in registers
#pragma unroll
    for (int mt = 0; mt < 4; ++mt)
#pragma unroll
        for (int n8 = 0; n8 < 8; ++n8)
#pragma unroll
            for (int k = 0; k < 4; ++k)
                acc[mt][n8][k] = __expf(acc[mt][n8][k] * 0.03125f);

    const long so = (long)z * SEQ * SEQ;
    const int wid = threadIdx.x >> 5, lane = threadIdx.x & 31;
    const int wm = wid & 1, wn = wid >> 1;
    const int rl = lane >> 2, cl = (lane & 3) * 2;
    float* rsbase = g_rowsum + (long)z * SEQ;

#pragma unroll
    for (int mt = 0; mt < 4; ++mt) {
        const long ra = bm + wm * 64 + mt * 16 + rl;
        float s0 = 0.0f, s1 = 0.0f;   // partial row sums over this thread's 16 cols
#pragma unroll
        for (int n8 = 0; n8 < 8; ++n8) {
            const int c = wn * 64 + n8 * 8 + cl;
            __half2 H0, H1;
            H0.x = __float2half_rn(acc[mt][n8][0]);
            H0.y = __float2half_rn(acc[mt][n8][1]);
            H1.x = __float2half_rn(acc[mt][n8][2]);
            H1.y = __float2half_rn(acc[mt][n8][3]);
            *(__half2*)(g_Ph + so + ra * SEQ + bn + c) = H0;
            *(__half2*)(g_Ph + so + (ra + 8) * SEQ + bn + c) = H1;
            s0 += acc[mt][n8][0] + acc[mt][n8][1];
            s1 += acc[mt][n8][2] + acc[mt][n8][3];
        }
        // quad reduction: lanes {q, q^1, q^2, q^3} hold the 4 col-pairs of rows ra/ra+8
        s0 += __shfl_xor_sync(0xffffffffu, s0, 1);
        s0 += __shfl_xor_sync(0xffffffffu, s0, 2);
        s1 += __shfl_xor_sync(0xffffffffu, s1, 1);
        s1 += __shfl_xor_sync(0xffffffffu, s1, 2);
        if ((lane & 3) == 0) {
            atomicAdd(&rsbase[ra], s0);
            atomicAdd(&rsbase[ra + 8], s1);
        }
    }
}

// ---------------- Kernel 3: out = (P̂ @ V) / rowsum — register epilogue ----------------
__global__ void __launch_bounds__(128, 2) pv_gemm_tc(float* __restrict__ out) {
    const int z = blockIdx.z;
    const long bm = (long)blockIdx.y * TM;
    const long bn = (long)blockIdx.x * TN;
    const long po = (long)z * SEQ * SEQ;
    const long vo = (long)z * DIM * SEQ;
    float acc[4][8][4];
    gemm1(g_Ph + po, g_Vth + vo, bm, bn, SEQ, acc);

    float* O = out + (long)z * SEQ * DIM;
    const float* rs = g_rowsum + (long)z * SEQ;
    const int wid = threadIdx.x >> 5, lane = threadIdx.x & 31;
    const int wm = wid & 1, wn = wid >> 1;
    const int rl = lane >> 2, cl = (lane & 3) * 2;
#pragma unroll
    for (int mt = 0; mt < 4; ++mt) {
        const long ra = bm + wm * 64 + mt * 16 + rl;
        const float ia = 1.0f / rs[ra];
        const float ib = 1.0f / rs[ra + 8];
#pragma unroll
        for (int n8 = 0; n8 < 8; ++n8) {
            const long c = bn + wn * 64 + n8 * 8 + cl;
            *(float2*)&O[ra * DIM + c] = make_float2(acc[mt][n8][0] * ia, acc[mt][n8][1] * ia);
            *(float2*)&O[(ra + 8) * DIM + c] = make_float2(acc[mt][n8][2] * ib, acc[mt][n8][3] * ib);
        }
    }
}

// ---------------------------------------------------------------------------
extern "C" void kernel_launch(void* const* d_in, const int* in_sizes, int n_in,
                              void* d_out, int out_size) {
    const float* x1 = nullptr;
    const float* W = nullptr;
    const float* bias = nullptr;
    for (int i = 0; i < n_in; i++) {
        if (in_sizes[i] == (int)(BATCH * SEQ * DIM)) x1 = (const float*)d_in[i];
        else if (in_sizes[i] == (int)(QKVN * DIM))   W = (const float*)d_in[i];
        else if (in_sizes[i] == QKVN)                bias = (const float*)d_in[i];
    }
    float* out = (float*)d_out;

    const int SM_BYTES = 96 * 1024;   // 3x32KB stages; fp32 stage overlay 67.6KB

    cudaFuncSetAttribute(qkv_gemm_tc, cudaFuncAttributeMaxDynamicSharedMemorySize, SM_BYTES);
    cudaFuncSetAttribute(scores_gemm_tc, cudaFuncAttributeMaxDynamicSharedMemorySize, SM_BYTES);
    cudaFuncSetAttribute(pv_gemm_tc, cudaFuncAttributeMaxDynamicSharedMemorySize, SM_BYTES);

    zero_rowsum<<<BATCH * SEQ / 256, 256>>>();
    convert_h<<<NELT_X / 1024, 256>>>(x1, 0);
    convert_h<<<NELT_W / 1024, 256>>>(W, 1);
    qkv_gemm_tc<<<dim3(QKVN / TN, (BATCH * SEQ) / TM), 128, SM_BYTES>>>(bias);
    scores_gemm_tc<<<dim3(SEQ / TN, SEQ / TM, BATCH), 128, SM_BYTES>>>();
    pv_gemm_tc<<<dim3(DIM / TN, SEQ / TM, BATCH), 128, SM_BYTES>>>(out);
}